// round 9
// baseline (speedup 1.0000x reference)
#include <cuda_runtime.h>
#include <cstdint>
#include <math.h>

// Problem dims (fixed)
#define BB   64
#define SS   1024
#define TT   256
#define VV   34
#define EE   256
#define HH   256
#define KVV  128
#define MHH  128

#define NBLK 128          // seq grid: 2 groups x 64 blocks
#define NTHR 1024

// Output layout (flat float32): y_hat [B,T,V], y_hat_label [B,T], labels_out [B,T], attentions [B,S,T]
#define OFF_Y   0
#define OFF_L   (BB*TT*VV)
#define OFF_LB  (OFF_L + BB*TT)
#define OFF_ATT (OFF_LB + BB*TT)

// ---------------- device globals (allocation-free scratch) ----------------
__device__ float d_h[2*3*BB*HH];             // double-buffered hidden
__device__ float d_c[3*BB*HH];               // cell state
__device__ float d_q[TT*BB*KVV];             // per-step query
__device__ float d_ctxh[2*TT*BB*KVV];        // per-step UNNORMALIZED ctx numerators (halves)
__device__ float d_att[TT*BB*SS];            // UNNORMALIZED attn exp(e) staged [t][b][s]
__device__ float d_zsum[TT*BB*2];            // softmax Z halves [t][b][half]
__device__ unsigned int g_cnt2[2][32];       // per-group barrier count (padded)
__device__ unsigned int g_gen2[2][32];       // per-group barrier generation (padded)

#define H_IDX(p,l,b,u)    (((((p)*3)+(l))*BB+(b))*HH+(u))
#define C_IDX(l,b,u)      ((((l)*BB)+(b))*HH+(u))
#define CTX_IDX(hf,t,b,k) (((((hf)*TT)+(t))*BB+(b))*KVV+(k))
#define Q_IDX(t,b,k)      ((((t)*BB)+(b))*KVV+(k))

// seq shared layout (floats)
#define OFFW    0         // 26624 : packed W [(k)*16+r] per layer, bases {0,10240,18432}
#define OFFX    26624     // 16512 : X tile (l0 emb 32x260 / l0 main 32x388 / l1,2 32x516)
#define OFFR    43136     // 4096  : reduction scratch [ks(8)][rq(4)][bl(32)][4]
#define OFFQ    47232     // 128   : query
#define OFFB    47360     // 48    : biases
#define OFFLAB  47408     // 32    : labels (int)
#define OFFR32  47440     // 32    : warp-reduce scratch
#define OFFZI   47472     // 32    : 1/Z per batch (for L0 ctx staging)
#define OFFTAIL 47504     // 128   : V tail sums (persistent)
#define SEQ_SMEM_FLOATS 47632
#define SEQ_SMEM_BYTES  (SEQ_SMEM_FLOATS*4)

// mlp shared layout (floats)
#define MOFFW  0          // 32768 : W_m1 128x256
#define MOFFX  32768      // 16640 : x 64x260 (reused as hid 64x132)
#define MOFFL  49408      // 2240  : logits 64x35
#define MOFFZ  51648      // 64    : 1/Z per batch
#define MLP_SMEM_FLOATS 51712
#define MLP_SMEM_BYTES  (MLP_SMEM_FLOATS*4)

__device__ __forceinline__ float sigm(float x) { return 1.0f / (1.0f + expf(-x)); }

// 64-block group barrier (sense-reversing, tight poll)
__device__ __forceinline__ void group_sync(int g)
{
    __syncthreads();
    if (threadIdx.x == 0) {
        __threadfence();
        unsigned int gen = *((volatile unsigned int*)&g_gen2[g][0]);
        if (atomicAdd(&g_cnt2[g][0], 1u) == 63u) {
            g_cnt2[g][0] = 0;
            __threadfence();
            *((volatile unsigned int*)&g_gen2[g][0]) = gen + 1u;
        } else {
            while (*((volatile unsigned int*)&g_gen2[g][0]) == gen) { }
            __threadfence();
        }
    }
    __syncthreads();
}

__global__ void dummy_kernel() {}

// ---------------------------------------------------------------------------
// persistent seq kernel: 2 groups x 64 blocks x 1024 threads, co-resident.
// Group g owns batches [g*32, g*32+32).
// LSTM: block (g, ug): 32 batches x 4 units of every layer, weights in smem,
//       8-way K-split over 1024 threads.
// Attention: block (g, wid0): batt = g*32+(wid0>>1), half = wid0&1.
//   Halves split the ACTIVE range [0,mylen) evenly (load-balanced);
//   masked rows handled once at init (d_att=1, Z count, V tail).
// ---------------------------------------------------------------------------
__global__ void __launch_bounds__(NTHR, 1)
seq_kernel(const float* __restrict__ enc_key, const float* __restrict__ enc_value,
           const int*   __restrict__ labels,  const int*   __restrict__ seq_lens,
           const float* __restrict__ emb,
           const float* __restrict__ W_ih0,   const float* __restrict__ W_hh0,
           const float* __restrict__ b_ih0,   const float* __restrict__ b_hh0,
           const float* __restrict__ W_ih_r,  const float* __restrict__ W_hh_r,
           const float* __restrict__ b_ih_r,  const float* __restrict__ b_hh_r,
           const float* __restrict__ W_fc,    const float* __restrict__ b_fc,
           const int*   __restrict__ sos)
{
    extern __shared__ float sm[];
    float* wsh    = sm + OFFW;
    float* Xs     = sm + OFFX;
    float* red    = sm + OFFR;
    float* qsh    = sm + OFFQ;
    float* bsh    = sm + OFFB;
    int*   labsh  = (int*)(sm + OFFLAB);
    float* r32    = sm + OFFR32;
    float* zish   = sm + OFFZI;
    float* tailsh = sm + OFFTAIL;

    const int tid  = threadIdx.x;
    const int blk  = blockIdx.x;
    const int g    = blk >> 6;
    const int wid0 = blk & 63;
    const int ug   = wid0;
    const int lane = tid & 31;
    const int wid  = tid >> 5;          // 0..31

    const int batt = g * 32 + (wid0 >> 1);
    const int half = wid0 & 1;

    // ---- per-group init: zero recurrent state ----
    {
        const int totH = 2 * 3 * 32 * HH;
        for (int i = wid0 * NTHR + tid; i < totH; i += 64 * NTHR) {
            int u = i & 255, r = i >> 8, bl2 = r & 31, pl = r >> 5;
            d_h[(pl * BB + (g * 32 + bl2)) * HH + u] = 0.0f;
        }
        const int totC = 3 * 32 * HH;
        for (int i = wid0 * NTHR + tid; i < totC; i += 64 * NTHR) {
            int u = i & 255, r = i >> 8, bl2 = r & 31, l = r >> 5;
            d_c[(l * BB + (g * 32 + bl2)) * HH + u] = 0.0f;
        }
    }

    // ---- pack this block's weights straight into shared: wsh[wbase+k*16+r] ----
    {
        for (int idx = tid; idx < 16 * 640; idx += NTHR) {
            int r = idx / 640, k = idx - r * 640;
            int gate = r & 3, ul = r >> 2;
            int grow = gate * 256 + ug * 4 + ul;
            float v = (k < 384) ? W_ih0[(size_t)grow * 384 + k] : W_hh0[(size_t)grow * 256 + (k - 384)];
            wsh[k * 16 + r] = v;
        }
        for (int l = 1; l < 3; l++) {
            int base = (l == 1) ? 10240 : 18432;
            for (int idx = tid; idx < 16 * 512; idx += NTHR) {
                int r = idx >> 9, k = idx & 511;
                int gate = r & 3, ul = r >> 2;
                int grow = gate * 256 + ug * 4 + ul;
                float v = (k < 256) ? W_ih_r[((size_t)(l - 1) * 1024 + grow) * 256 + k]
                                    : W_hh_r[((size_t)(l - 1) * 1024 + grow) * 256 + (k - 256)];
                wsh[base + k * 16 + r] = v;
            }
        }
        if (tid < 48) {
            int l = tid >> 4, r = tid & 15;
            int gate = r & 3, ul = r >> 2;
            int grow = gate * 256 + ug * 4 + ul;
            bsh[tid] = (l == 0) ? (b_ih0[grow] + b_hh0[grow])
                                : (b_ih_r[(l - 1) * 1024 + grow] + b_hh_r[(l - 1) * 1024 + grow]);
        }
    }

    const int mylen = seq_lens[batt];
    // masked-row count in this half's STATIC range (Z contribution, t-invariant)
    int tz = mylen - half * 512; tz = tz < 0 ? 0 : (tz > 512 ? 512 : tz);
    const float tailZ = (float)(512 - tz);
    // active-range split for balanced halves
    const int A0 = (mylen + 1) >> 1;
    const int row_off = half ? A0 : 0;
    const int cnt     = half ? (mylen - A0) : A0;

    // ---- V tail sums over this half's STATIC range (t-invariant) ----
    {
        const int sbase = half * 512 + wid * 16;
        int act = mylen - sbase; act = act < 0 ? 0 : (act > 16 ? 16 : act);
        const float4* vb4 = (const float4*)(enc_value + ((size_t)batt * SS + sbase) * KVV);
        float4 tacc; tacc.x = tacc.y = tacc.z = tacc.w = 0.f;
        for (int r = act; r < 16; r++) {
            float4 vv = vb4[r * 32 + lane];
            tacc.x += vv.x; tacc.y += vv.y; tacc.z += vv.z; tacc.w += vv.w;
        }
        *(float4*)&red[wid * 128 + lane * 4] = tacc;
    }
    __syncthreads();
    if (tid < 128) {
        float s = 0.f;
        #pragma unroll
        for (int w = 0; w < 32; w++) s += red[w * 128 + tid];
        tailsh[tid] = s;
    }

    // ---- masked d_att rows = 1.0 for ALL t (t-invariant), written once ----
    {
        const int nmask = SS - mylen;                       // s in [mylen, SS)
        const int tlo = half * (TT / 2), thi = tlo + TT / 2;
        for (int tt2 = tlo; tt2 < thi; tt2++) {
            float* ap = &d_att[((size_t)tt2 * BB + batt) * SS + mylen];
            for (int s = tid; s < nmask; s += NTHR) ap[s] = 1.0f;
        }
    }
    group_sync(g);

    // GEMM thread mapping (fixed across phases): 8-way K split
    const int bl = tid & 31;
    const int rq = (tid >> 5) & 3;
    const int ks = tid >> 7;           // 0..7

    // ---- pre-loop: labels for t=0 (SOS), emb-part precompute ----
    if (tid < 32) labsh[tid] = sos[0];
    __syncthreads();

    float accP0, accP1, accP2, accP3;
    {
        for (int idx = tid; idx < 32 * 64; idx += NTHR) {
            int b2 = idx >> 6, k4 = idx & 63;
            float4 v = ((const float4*)emb)[(size_t)labsh[b2] * 64 + k4];
            *(float4*)&Xs[b2 * 260 + k4 * 4] = v;
        }
        __syncthreads();
        const float* xp  = Xs + bl * 260 + ks * 32;
        const float* wp0 = wsh + (ks * 32) * 16 + rq * 4;
        float a0 = 0.f, a1 = 0.f, a2 = 0.f, a3 = 0.f;
        #pragma unroll
        for (int k0 = 0; k0 < 32; k0 += 4) {
            float4 x4 = *(const float4*)(xp + k0);
            const float* wq = wp0 + k0 * 16;
            float4 w0 = *(const float4*)(wq);
            float4 w1 = *(const float4*)(wq + 16);
            float4 w2 = *(const float4*)(wq + 32);
            float4 w3 = *(const float4*)(wq + 48);
            a0 += w0.x * x4.x + w1.x * x4.y + w2.x * x4.z + w3.x * x4.w;
            a1 += w0.y * x4.x + w1.y * x4.y + w2.y * x4.z + w3.y * x4.w;
            a2 += w0.z * x4.x + w1.z * x4.y + w2.z * x4.z + w3.z * x4.w;
            a3 += w0.w * x4.x + w1.w * x4.y + w2.w * x4.z + w3.w * x4.w;
        }
        accP0 = a0; accP1 = a1; accP2 = a2; accP3 = a3;
    }
    __syncthreads();

    for (int t = 0; t < TT; t++) {
        const int rp = t & 1, wp = rp ^ 1;

        // 1/Z per batch for ctx normalization (from t-1)
        if (t > 0 && tid < 32) {
            int b = g * 32 + tid;
            float z0 = d_zsum[((size_t)(t - 1) * BB + b) * 2 + 0];
            float z1 = d_zsum[((size_t)(t - 1) * BB + b) * 2 + 1];
            zish[tid] = 1.0f / (z0 + z1);
        }
        __syncthreads();

        // ================= LSTM L0 (main part: ctx + h0, K=384) =================
        {
            for (int idx = tid; idx < 32 * 96; idx += NTHR) {
                int b2 = idx / 96, k4 = idx - b2 * 96;
                int b = g * 32 + b2;
                float4 v;
                if (k4 < 32) {
                    if (t == 0) { v.x = v.y = v.z = v.w = 0.0f; }
                    else {
                        float4 a  = *(const float4*)&d_ctxh[CTX_IDX(0, t - 1, b, k4 * 4)];
                        float4 c2 = *(const float4*)&d_ctxh[CTX_IDX(1, t - 1, b, k4 * 4)];
                        float zi = zish[b2];
                        v.x = (a.x + c2.x) * zi; v.y = (a.y + c2.y) * zi;
                        v.z = (a.z + c2.z) * zi; v.w = (a.w + c2.w) * zi;
                    }
                } else {
                    v = *(const float4*)&d_h[H_IDX(rp, 0, b, (k4 - 32) * 4)];
                }
                *(float4*)&Xs[b2 * 388 + k4 * 4] = v;
            }
            __syncthreads();
            const float* xp  = Xs + bl * 388 + ks * 48;
            const float* wp0 = wsh + (256 + ks * 48) * 16 + rq * 4;
            float a0 = accP0, a1 = accP1, a2 = accP2, a3 = accP3;
            #pragma unroll 4
            for (int k0 = 0; k0 < 48; k0 += 4) {
                float4 x4 = *(const float4*)(xp + k0);
                const float* wq = wp0 + k0 * 16;
                float4 w0 = *(const float4*)(wq);
                float4 w1 = *(const float4*)(wq + 16);
                float4 w2 = *(const float4*)(wq + 32);
                float4 w3 = *(const float4*)(wq + 48);
                a0 += w0.x * x4.x + w1.x * x4.y + w2.x * x4.z + w3.x * x4.w;
                a1 += w0.y * x4.x + w1.y * x4.y + w2.y * x4.z + w3.y * x4.w;
                a2 += w0.z * x4.x + w1.z * x4.y + w2.z * x4.z + w3.z * x4.w;
                a3 += w0.w * x4.x + w1.w * x4.y + w2.w * x4.z + w3.w * x4.w;
            }
            float4 rv; rv.x = a0; rv.y = a1; rv.z = a2; rv.w = a3;
            *(float4*)&red[ks * 512 + rq * 128 + bl * 4] = rv;
            __syncthreads();
            if (tid < 128) {
                const int b2 = tid & 31, rq2 = tid >> 5;
                float gi = bsh[rq2 * 4 + 0], gf = bsh[rq2 * 4 + 1], gg = bsh[rq2 * 4 + 2], go = bsh[rq2 * 4 + 3];
                #pragma unroll
                for (int kk = 0; kk < 8; kk++) {
                    float4 v = *(const float4*)&red[kk * 512 + rq2 * 128 + b2 * 4];
                    gi += v.x; gf += v.y; gg += v.z; go += v.w;
                }
                const int u = ug * 4 + rq2;
                const int b = g * 32 + b2;
                float cn = sigm(gf) * d_c[C_IDX(0, b, u)] + sigm(gi) * tanhf(gg);
                d_c[C_IDX(0, b, u)] = cn;
                d_h[H_IDX(wp, 0, b, u)] = sigm(go) * tanhf(cn);
            }
            group_sync(g);
        }

        // ================= LSTM L1, L2 (K=512) =================
        #pragma unroll 1
        for (int l = 1; l < 3; l++) {
            const int base = (l == 1) ? 10240 : 18432;
            for (int idx = tid; idx < 32 * 128; idx += NTHR) {
                int b2 = idx >> 7, k4 = idx & 127;
                int b = g * 32 + b2;
                float4 v = (k4 < 64) ? *(const float4*)&d_h[H_IDX(wp, l - 1, b, k4 * 4)]
                                     : *(const float4*)&d_h[H_IDX(rp, l, b, (k4 - 64) * 4)];
                *(float4*)&Xs[b2 * 516 + k4 * 4] = v;
            }
            __syncthreads();
            const float* xp  = Xs + bl * 516 + ks * 64;
            const float* wp0 = wsh + base + (ks * 64) * 16 + rq * 4;
            float a0 = 0.f, a1 = 0.f, a2 = 0.f, a3 = 0.f;
            #pragma unroll 4
            for (int k0 = 0; k0 < 64; k0 += 4) {
                float4 x4 = *(const float4*)(xp + k0);
                const float* wq = wp0 + k0 * 16;
                float4 w0 = *(const float4*)(wq);
                float4 w1 = *(const float4*)(wq + 16);
                float4 w2 = *(const float4*)(wq + 32);
                float4 w3 = *(const float4*)(wq + 48);
                a0 += w0.x * x4.x + w1.x * x4.y + w2.x * x4.z + w3.x * x4.w;
                a1 += w0.y * x4.x + w1.y * x4.y + w2.y * x4.z + w3.y * x4.w;
                a2 += w0.z * x4.x + w1.z * x4.y + w2.z * x4.z + w3.z * x4.w;
                a3 += w0.w * x4.x + w1.w * x4.y + w2.w * x4.z + w3.w * x4.w;
            }
            float4 rv; rv.x = a0; rv.y = a1; rv.z = a2; rv.w = a3;
            *(float4*)&red[ks * 512 + rq * 128 + bl * 4] = rv;
            __syncthreads();
            if (tid < 128) {
                const int b2 = tid & 31, rq2 = tid >> 5;
                float gi = bsh[l * 16 + rq2 * 4 + 0], gf = bsh[l * 16 + rq2 * 4 + 1];
                float gg = bsh[l * 16 + rq2 * 4 + 2], go = bsh[l * 16 + rq2 * 4 + 3];
                #pragma unroll
                for (int kk = 0; kk < 8; kk++) {
                    float4 v = *(const float4*)&red[kk * 512 + rq2 * 128 + b2 * 4];
                    gi += v.x; gf += v.y; gg += v.z; go += v.w;
                }
                const int u = ug * 4 + rq2;
                const int b = g * 32 + b2;
                float cn = sigm(gf) * d_c[C_IDX(l, b, u)] + sigm(gi) * tanhf(gg);
                d_c[C_IDX(l, b, u)] = cn;
                d_h[H_IDX(wp, l, b, u)] = sigm(go) * tanhf(cn);
            }
            group_sync(g);
        }

        // ================= attention: single fused pass, balanced halves =================
        const float* h2 = &d_h[H_IDX(wp, 2, batt, 0)];

        // query partials (8-way K-split over 1024 threads)
        {
            const int c = tid & 127, s8 = tid >> 7;
            const float4* w4 = (const float4*)(W_fc + (size_t)c * HH + s8 * 32);
            const float4* h4 = (const float4*)(h2 + s8 * 32);
            float p = 0.f;
            #pragma unroll
            for (int k = 0; k < 8; k++) {
                float4 w = w4[k], hv = h4[k];
                p += w.x * hv.x + w.y * hv.y + w.z * hv.z + w.w * hv.w;
            }
            red[s8 * 128 + c] = p;
        }
        __syncthreads();
        if (tid < 128) {
            float q = b_fc[tid];
            #pragma unroll
            for (int s8 = 0; s8 < 8; s8++) q += red[s8 * 128 + tid];
            qsh[tid] = q;
            if (!half) d_q[Q_IDX(t, batt, tid)] = q;
        }
        __syncthreads();

        // fused energy -> exp -> numerator/Z over assigned active rows
        {
            float4 q4 = ((const float4*)qsh)[lane];
            int nrow = cnt - wid * 16; nrow = nrow < 0 ? 0 : (nrow > 16 ? 16 : nrow);
            const int rowbase = row_off + wid * 16;
            const float4* kb4 = (const float4*)(enc_key   + ((size_t)batt * SS + rowbase) * KVV);
            const float4* vb4 = (const float4*)(enc_value + ((size_t)batt * SS + rowbase) * KVV);
            float* attp = &d_att[((size_t)t * BB + batt) * SS + rowbase];

            float4 acc; acc.x = acc.y = acc.z = acc.w = 0.f;
            float zacc = 0.f;

            for (int rb = 0; rb < nrow; rb += 4) {
                float p[4];
                #pragma unroll
                for (int i = 0; i < 4; i++) {
                    bool a = (rb + i) < nrow;
                    float4 kv; kv.x = kv.y = kv.z = kv.w = 0.f;
                    if (a) kv = kb4[(rb + i) * 32 + lane];
                    p[i] = kv.x * q4.x + kv.y * q4.y + kv.z * q4.z + kv.w * q4.w;
                }
                #pragma unroll
                for (int off = 16; off; off >>= 1) {
                    #pragma unroll
                    for (int i = 0; i < 4; i++) p[i] += __shfl_xor_sync(0xffffffffu, p[i], off);
                }
                #pragma unroll
                for (int i = 0; i < 4; i++) {
                    bool a = (rb + i) < nrow;
                    float pv = a ? __expf(p[i]) : 0.0f;
                    float4 vv; vv.x = vv.y = vv.z = vv.w = 0.f;
                    if (a) vv = vb4[(rb + i) * 32 + lane];
                    acc.x += pv * vv.x; acc.y += pv * vv.y;
                    acc.z += pv * vv.z; acc.w += pv * vv.w;
                    zacc += pv;
                    if (a && lane == rb + i) attp[rb + i] = pv;
                }
            }

            *(float4*)&red[wid * 128 + lane * 4] = acc;
            if (lane == 0) r32[wid] = zacc;
        }
        __syncthreads();
        if (tid < 128) {
            float cx = tailsh[tid];
            #pragma unroll
            for (int w = 0; w < 32; w++) cx += red[w * 128 + tid];
            d_ctxh[CTX_IDX(half, t, batt, tid)] = cx;      // unnormalized numerator
        }
        if (tid == 0) {
            float z = tailZ;
            #pragma unroll
            for (int w = 0; w < 32; w++) z += r32[w];
            d_zsum[((size_t)t * BB + batt) * 2 + half] = z;
        }

        // ============ precompute next step's emb-part of L0 ============
        if (tid < 32) labsh[tid] = labels[t * BB + g * 32 + tid];
        __syncthreads();
        {
            for (int idx = tid; idx < 32 * 64; idx += NTHR) {
                int b2 = idx >> 6, k4 = idx & 63;
                float4 v = ((const float4*)emb)[(size_t)labsh[b2] * 64 + k4];
                *(float4*)&Xs[b2 * 260 + k4 * 4] = v;
            }
            __syncthreads();
            const float* xp  = Xs + bl * 260 + ks * 32;
            const float* wp0 = wsh + (ks * 32) * 16 + rq * 4;
            float a0 = 0.f, a1 = 0.f, a2 = 0.f, a3 = 0.f;
            #pragma unroll
            for (int k0 = 0; k0 < 32; k0 += 4) {
                float4 x4 = *(const float4*)(xp + k0);
                const float* wq = wp0 + k0 * 16;
                float4 w0 = *(const float4*)(wq);
                float4 w1 = *(const float4*)(wq + 16);
                float4 w2 = *(const float4*)(wq + 32);
                float4 w3 = *(const float4*)(wq + 48);
                a0 += w0.x * x4.x + w1.x * x4.y + w2.x * x4.z + w3.x * x4.w;
                a1 += w0.y * x4.x + w1.y * x4.y + w2.y * x4.z + w3.y * x4.w;
                a2 += w0.z * x4.x + w1.z * x4.y + w2.z * x4.z + w3.z * x4.w;
                a3 += w0.w * x4.x + w1.w * x4.y + w2.w * x4.z + w3.w * x4.w;
            }
            accP0 = a0; accP1 = a1; accP2 = a2; accP3 = a3;
        }

        group_sync(g);   // ctx numerators + Z + h visible for step t+1
    }
}

// ---------------------------------------------------------------------------
// Deferred MLP per timestep: 256 blocks x 512 threads, FMA-bound shared GEMM
// ---------------------------------------------------------------------------
__global__ void __launch_bounds__(512, 1)
mlp_kernel(const float* __restrict__ W_m1, const float* __restrict__ b_m1,
           const float* __restrict__ W_m2, const float* __restrict__ b_m2,
           const int*   __restrict__ labels,
           float* __restrict__ out)
{
    extern __shared__ float sm[];
    float* wsh1 = sm + MOFFW;     // [128][256]
    float* xsh  = sm + MOFFX;     // [64][260], reused as hid [64][132]
    float* lsh  = sm + MOFFL;     // [64][35]
    float* zk   = sm + MOFFZ;     // [64]

    const int t   = blockIdx.x;
    const int tid = threadIdx.x;

    {
        const float4* src = (const float4*)W_m1;
        float4* dst = (float4*)wsh1;
        for (int idx = tid; idx < 128 * 256 / 4; idx += 512) dst[idx] = src[idx];
    }
    if (tid < 64) {
        float z0 = d_zsum[((size_t)t * BB + tid) * 2 + 0];
        float z1 = d_zsum[((size_t)t * BB + tid) * 2 + 1];
        zk[tid] = 1.0f / (z0 + z1);
    }
    __syncthreads();
    for (int idx = tid; idx < 64 * 256; idx += 512) {
        int bb = idx >> 8, k = idx & 255;
        float v = (k < 128) ? d_q[Q_IDX(t, bb, k)]
                            : (d_ctxh[CTX_IDX(0, t, bb, k - 128)] + d_ctxh[CTX_IDX(1, t, bb, k - 128)]) * zk[bb];
        xsh[bb * 260 + k] = v;
    }
    __syncthreads();

    const int b  = tid & 63;
    const int rq = tid >> 6;       // 0..7
    float acc[16];
    #pragma unroll
    for (int j = 0; j < 16; j++) acc[j] = 0.f;
    for (int k = 0; k < 256; k += 4) {
        float4 x4 = *(const float4*)(xsh + b * 260 + k);
        #pragma unroll
        for (int j = 0; j < 16; j++) {
            float4 w = *(const float4*)(wsh1 + (rq * 16 + j) * 256 + k);
            acc[j] += w.x * x4.x + w.y * x4.y + w.z * x4.z + w.w * x4.w;
        }
    }
    __syncthreads();

    #pragma unroll
    for (int j = 0; j < 16; j++) {
        int c = rq * 16 + j;
        float hv = acc[j] + b_m1[c];
        hv = (hv >= 0.0f) ? hv : 0.9f * hv;
        xsh[b * 132 + c] = hv;
    }
    __syncthreads();

    for (int i = tid; i < BB * VV; i += 512) {
        int b2 = i & 63, v = i >> 6;
        float a = b_m2[v];
        const float4* w4 = (const float4*)(W_m2 + (size_t)v * MHH);
        const float4* h4 = (const float4*)(xsh + b2 * 132);
        #pragma unroll 8
        for (int k = 0; k < 32; k++) {
            float4 w = w4[k], hv = h4[k];
            a += w.x * hv.x + w.y * hv.y + w.z * hv.z + w.w * hv.w;
        }
        out[OFF_Y + ((size_t)b2 * TT + t) * VV + v] = a;
        lsh[b2 * 35 + v] = a;
    }
    __syncthreads();

    if (tid < BB) {
        float best = lsh[tid * 35]; int bi = 0;
        #pragma unroll
        for (int v = 1; v < VV; v++) {
            float lv = lsh[tid * 35 + v];
            if (lv > best) { best = lv; bi = v; }
        }
        out[OFF_L  + (size_t)tid * TT + t] = (float)bi;
        out[OFF_LB + (size_t)tid * TT + t] = (float)labels[t * BB + tid];
    }
}

// ---------------------------------------------------------------------------
// attn transpose + normalize: d_att [t][b][s] * (1/Z[t][b]) -> out [b][s][t]
// ---------------------------------------------------------------------------
__global__ void __launch_bounds__(256, 4)
att_transpose(float* __restrict__ out_att)
{
    __shared__ float tile[32][33];
    __shared__ float zsh[32];
    const int tt = blockIdx.x;    // t-tile (8)
    const int st = blockIdx.y;    // s-tile (32)
    const int b  = blockIdx.z;    // batch (64)
    const int tx = threadIdx.x & 31;
    const int ty = threadIdx.x >> 5;   // 0..7

    if (threadIdx.x < 32) {
        int trow = tt * 32 + threadIdx.x;
        float z0 = d_zsum[((size_t)trow * BB + b) * 2 + 0];
        float z1 = d_zsum[((size_t)trow * BB + b) * 2 + 1];
        zsh[threadIdx.x] = 1.0f / (z0 + z1);
    }
    __syncthreads();

    #pragma unroll
    for (int i = 0; i < 4; i++) {
        int trow = tt * 32 + ty + i * 8;
        tile[ty + i * 8][tx] = d_att[((size_t)trow * BB + b) * SS + st * 32 + tx];
    }
    __syncthreads();
    #pragma unroll
    for (int i = 0; i < 4; i++) {
        int srow = st * 32 + ty + i * 8;
        out_att[((size_t)b * SS + srow) * TT + tt * 32 + tx] = tile[tx][ty + i * 8] * zsh[tx];
    }
}

extern "C" void kernel_launch(void* const* d_in, const int* in_sizes, int n_in,
                              void* d_out, int out_size)
{
    const float* enc_key   = (const float*)d_in[0];
    const float* enc_value = (const float*)d_in[1];
    const int*   labels    = (const int*)  d_in[2];
    const int*   seq_lens  = (const int*)  d_in[3];
    const float* emb       = (const float*)d_in[4];
    const float* W_ih0     = (const float*)d_in[5];
    const float* W_hh0     = (const float*)d_in[6];
    const float* b_ih0     = (const float*)d_in[7];
    const float* b_hh0     = (const float*)d_in[8];
    const float* W_ih_r    = (const float*)d_in[9];
    const float* W_hh_r    = (const float*)d_in[10];
    const float* b_ih_r    = (const float*)d_in[11];
    const float* b_hh_r    = (const float*)d_in[12];
    const float* W_fc      = (const float*)d_in[13];
    const float* b_fc      = (const float*)d_in[14];
    const float* W_m1      = (const float*)d_in[15];
    const float* b_m1      = (const float*)d_in[16];
    const float* W_m2      = (const float*)d_in[17];
    const float* b_m2      = (const float*)d_in[18];
    const int*   sos       = (const int*)  d_in[19];

    float* out = (float*)d_out;

    cudaFuncSetAttribute(seq_kernel, cudaFuncAttributeMaxDynamicSharedMemorySize, SEQ_SMEM_BYTES);
    cudaFuncSetAttribute(mlp_kernel, cudaFuncAttributeMaxDynamicSharedMemorySize, MLP_SMEM_BYTES);

    // [d,d,d,seq,mlp,trans]: -s 5 capture lands at call-position 3 = seq_kernel.
    dummy_kernel<<<1, 32>>>();
    dummy_kernel<<<1, 32>>>();
    dummy_kernel<<<1, 32>>>();

    seq_kernel<<<NBLK, NTHR, SEQ_SMEM_BYTES>>>(enc_key, enc_value, labels, seq_lens, emb,
                                               W_ih0, W_hh0, b_ih0, b_hh0,
                                               W_ih_r, W_hh_r, b_ih_r, b_hh_r,
                                               W_fc, b_fc, sos);

    mlp_kernel<<<TT, 512, MLP_SMEM_BYTES>>>(W_m1, b_m1, W_m2, b_m2, labels, out);

    dim3 tgrid(8, 32, 64);
    att_transpose<<<tgrid, 256>>>(out + OFF_ATT);
}